// round 2
// baseline (speedup 1.0000x reference)
#include <cuda_runtime.h>
#include <cstdint>

// ---------------------------------------------------------------------------
// GE2E loss, fixed shapes: N_SPK=1024, N_UTT=32, D=128
//   loss = mean over 32768 rows of ( logsumexp_k(logit) - logit_target )
//   logit[i][k] = w * cos(e_i, cent_k) + b,  except k==spk(i) uses exclusive
//   centroid.
// ---------------------------------------------------------------------------

#define NS 1024
#define NU 32
#define DD 128
#define NROWS (NS * NU)          // 32768
#define EPS 1e-8f

// scratch (device globals; no allocations allowed)
__device__ __align__(16) float g_ehat[NROWS * DD];     // 16 MB, e / ||e||
__device__ __align__(16) float g_chatT[DD * NS];       // 512 KB, transposed cent/||cent||
__device__ __align__(16) float g_ownlogit[NROWS];      // substituted own-column logit
__device__ __align__(16) float g_partial[NROWS / 64];  // per-block partial losses (512)

// ---- f32x2 packed math helpers -------------------------------------------
#define PACK_F32X2(out, lo, hi) \
    asm("mov.b64 %0, {%1, %2};" : "=l"(out) : "f"(lo), "f"(hi))
#define UNPACK_F32X2(lo, hi, in) \
    asm("mov.b64 {%0, %1}, %2;" : "=f"(lo), "=f"(hi) : "l"(in))
#define FMA_F32X2(d, a, b, c) \
    asm("fma.rn.f32x2 %0, %1, %2, %3;" : "=l"(d) : "l"(a), "l"(b), "l"(c))

// ---- cp.async helpers ------------------------------------------------------
__device__ __forceinline__ uint32_t smem_u32(const void* p) {
    uint32_t a;
    asm("{ .reg .u64 t; cvta.to.shared.u64 t, %1; cvt.u32.u64 %0, t; }"
        : "=r"(a) : "l"(p));
    return a;
}
#define CP_ASYNC16(dst_u32, src_ptr) \
    asm volatile("cp.async.ca.shared.global [%0], [%1], 16;" :: "r"(dst_u32), "l"(src_ptr))
#define CP_COMMIT() asm volatile("cp.async.commit_group;")
#define CP_WAIT(n)  asm volatile("cp.async.wait_group %0;" :: "n"(n))

// ===========================================================================
// Kernel 1: per-speaker centroid, exclusive-centroid own logits, ehat, chatT
// grid = 1024 blocks (one speaker), 128 threads
// ===========================================================================
__global__ void __launch_bounds__(128) k_centroids(const float* __restrict__ emb,
                                                   const float* __restrict__ wp,
                                                   const float* __restrict__ bp) {
    __shared__ float es[NU][DD];     // 16 KB
    __shared__ float S[DD];
    __shared__ float red[4];
    __shared__ float s2_sh;
    __shared__ float en_inv[NU];

    const int n = blockIdx.x;
    const int t = threadIdx.x;
    const float* base = emb + (size_t)n * NU * DD;

    float s = 0.f;
#pragma unroll
    for (int m = 0; m < NU; m++) {
        float v = base[m * DD + t];
        es[m][t] = v;
        s += v;
    }
    S[t] = s;

    // |S|^2 block reduce
    float v = s * s;
#pragma unroll
    for (int o = 16; o > 0; o >>= 1) v += __shfl_xor_sync(0xffffffffu, v, o);
    if ((t & 31) == 0) red[t >> 5] = v;
    __syncthreads();
    if (t == 0) s2_sh = red[0] + red[1] + red[2] + red[3];
    __syncthreads();
    const float S2 = s2_sh;
    const float w = *wp, b = *bp;

    // chat (transposed store for coalesced GEMM loads)
    {
        float cn = fmaxf(sqrtf(S2) * (1.f / NU), EPS);
        g_chatT[t * NS + n] = (S[t] * (1.f / NU)) / cn;
    }

    // per-utterance dot(e,S), |e|^2 -> own logit + 1/||e||
    const int wq = t >> 5, lane = t & 31;
#pragma unroll
    for (int mi = 0; mi < 8; mi++) {
        int m = wq * 8 + mi;
        float dot = 0.f, e2 = 0.f;
#pragma unroll
        for (int c = 0; c < 4; c++) {
            float ev = es[m][lane * 4 + c];
            dot += ev * S[lane * 4 + c];
            e2 += ev * ev;
        }
#pragma unroll
        for (int o = 16; o > 0; o >>= 1) {
            dot += __shfl_xor_sync(0xffffffffu, dot, o);
            e2  += __shfl_xor_sync(0xffffffffu, e2, o);
        }
        if (lane == 0) {
            float en = fmaxf(sqrtf(e2), EPS);
            float d2 = fmaxf(S2 - 2.f * dot + e2, 0.f);     // ||S - e||^2
            float cen = fmaxf(sqrtf(d2) * (1.f / (NU - 1)), EPS);
            float sim = ((dot - e2) * (1.f / (NU - 1))) / (en * cen);
            g_ownlogit[n * NU + m] = w * sim + b;
            en_inv[m] = 1.f / en;
        }
    }
    __syncthreads();

#pragma unroll
    for (int m = 0; m < NU; m++)
        g_ehat[((size_t)n * NU + m) * DD + t] = es[m][t] * en_inv[m];
}

// ===========================================================================
// Kernel 2: fused cosine GEMM (32768x1024, K=128) + online logsumexp + loss
// grid = 512 blocks (64 rows each), 256 threads; smem = A(32KB) + 2*B(64KB)
// warp layout: warp wq owns 8 rows; lane owns 4 cols of the 128-col chunk
// ===========================================================================
#define BM 64
#define CH 128
#define SMEM2_BYTES ((BM * DD + 2 * CH * DD) * 4)   // 160 KB

__global__ void __launch_bounds__(256, 1) k_gemm_softmax(const float* __restrict__ wp,
                                                         const float* __restrict__ bp) {
    extern __shared__ float sm[];
    float* as_ = sm;                 // [64][128]
    float* bs  = sm + BM * DD;       // [2][128][128] layout [d][col]

    const int tid = threadIdx.x, wq = tid >> 5, lane = tid & 31;
    const int rb = blockIdx.x * BM;

    // ---- stage A tile + B chunk 0 (group 0) ----
    {
        uint32_t sa = smem_u32(as_);
        const float* g = g_ehat + (size_t)rb * DD;
#pragma unroll
        for (int i = 0; i < 8; i++) {          // 2048 float4
            uint32_t idx = (uint32_t)(tid + i * 256);
            CP_ASYNC16(sa + idx * 16u, g + idx * 4);
        }
        uint32_t sb = smem_u32(bs);
#pragma unroll
        for (int i = 0; i < 16; i++) {         // 4096 float4
            uint32_t idx = (uint32_t)(tid + i * 256);
            int d = (int)(idx >> 5), c4 = (int)(idx & 31);
            CP_ASYNC16(sb + idx * 16u, g_chatT + d * NS + 0 + c4 * 4);
        }
        CP_COMMIT();
    }

    const float w = *wp, bb = *bp;
    const int rowg0 = rb + wq * 8;
    const int nspk = rowg0 >> 5;   // same speaker for all 8 rows of this warp

    float ol[8];
#pragma unroll
    for (int r = 0; r < 8; r++) ol[r] = g_ownlogit[rowg0 + r];

    float mrun[8], srun[8];
#pragma unroll
    for (int r = 0; r < 8; r++) { mrun[r] = -INFINITY; srun[r] = 0.f; }

    for (int ci = 0; ci < 8; ci++) {
        // prefetch next chunk into the other buffer
        if (ci + 1 < 8) {
            uint32_t sb = smem_u32(bs) + (uint32_t)(((ci + 1) & 1) * CH * DD * 4);
            int cb = (ci + 1) * CH;
#pragma unroll
            for (int i = 0; i < 16; i++) {
                uint32_t idx = (uint32_t)(tid + i * 256);
                int d = (int)(idx >> 5), c4 = (int)(idx & 31);
                CP_ASYNC16(sb + idx * 16u, g_chatT + d * NS + cb + c4 * 4);
            }
            CP_COMMIT();
            CP_WAIT(1);
        } else {
            CP_WAIT(0);
        }
        __syncthreads();

        const float* B = bs + (ci & 1) * CH * DD;
        const float* Arow = as_ + (wq * 8) * DD;

        unsigned long long acc[8][2];
#pragma unroll
        for (int r = 0; r < 8; r++) { acc[r][0] = 0ull; acc[r][1] = 0ull; }

#pragma unroll 4
        for (int d4 = 0; d4 < 32; d4++) {
            float4 a[8];
#pragma unroll
            for (int r = 0; r < 8; r++)
                a[r] = *(const float4*)(Arow + r * DD + d4 * 4);
#pragma unroll
            for (int c = 0; c < 4; c++) {
                float4 bv = *(const float4*)(B + (d4 * 4 + c) * CH + lane * 4);
                unsigned long long b01, b23;
                PACK_F32X2(b01, bv.x, bv.y);
                PACK_F32X2(b23, bv.z, bv.w);
#pragma unroll
                for (int r = 0; r < 8; r++) {
                    float av = (c == 0) ? a[r].x : (c == 1) ? a[r].y
                             : (c == 2) ? a[r].z : a[r].w;
                    unsigned long long a2;
                    PACK_F32X2(a2, av, av);
                    FMA_F32X2(acc[r][0], a2, b01, acc[r][0]);
                    FMA_F32X2(acc[r][1], a2, b23, acc[r][1]);
                }
            }
        }

        // ---- epilogue: logits, own-column substitution, online logsumexp ----
        float l[8][4];
#pragma unroll
        for (int r = 0; r < 8; r++) {
            UNPACK_F32X2(l[r][0], l[r][1], acc[r][0]);
            UNPACK_F32X2(l[r][2], l[r][3], acc[r][1]);
#pragma unroll
            for (int j = 0; j < 4; j++) l[r][j] = fmaf(w, l[r][j], bb);
        }
        int oc = nspk - ci * CH;                 // own col within this chunk?
        if (oc >= 0 && oc < CH && (oc >> 2) == lane) {
#pragma unroll
            for (int r = 0; r < 8; r++) l[r][oc & 3] = ol[r];
        }
#pragma unroll
        for (int r = 0; r < 8; r++) {
            float lm = fmaxf(fmaxf(l[r][0], l[r][1]), fmaxf(l[r][2], l[r][3]));
#pragma unroll
            for (int o = 16; o > 0; o >>= 1)
                lm = fmaxf(lm, __shfl_xor_sync(0xffffffffu, lm, o));
            float Mn = fmaxf(mrun[r], lm);
            float es = __expf(l[r][0] - Mn) + __expf(l[r][1] - Mn)
                     + __expf(l[r][2] - Mn) + __expf(l[r][3] - Mn);
#pragma unroll
            for (int o = 16; o > 0; o >>= 1)
                es += __shfl_xor_sync(0xffffffffu, es, o);
            srun[r] = srun[r] * __expf(mrun[r] - Mn) + es;
            mrun[r] = Mn;
        }
        __syncthreads();   // all warps done with bs[ci&1] before refill
    }

    // per-warp loss, block reduce, deterministic per-block partial
    __shared__ float wpart[8];
    float loss = 0.f;
#pragma unroll
    for (int r = 0; r < 8; r++)
        loss += mrun[r] + logf(srun[r]) - ol[r];
    if (lane == 0) wpart[wq] = loss;
    __syncthreads();
    if (tid == 0) {
        float tsum = 0.f;
#pragma unroll
        for (int i = 0; i < 8; i++) tsum += wpart[i];
        g_partial[blockIdx.x] = tsum;
    }
}

// ===========================================================================
// Kernel 3: reduce 512 partials -> loss mean
// ===========================================================================
__global__ void __launch_bounds__(512) k_reduce(float* __restrict__ out) {
    const int t = threadIdx.x;
    float v = g_partial[t];
#pragma unroll
    for (int o = 16; o > 0; o >>= 1) v += __shfl_xor_sync(0xffffffffu, v, o);
    __shared__ float red[16];
    if ((t & 31) == 0) red[t >> 5] = v;
    __syncthreads();
    if (t < 16) {
        float x = red[t];
#pragma unroll
        for (int o = 8; o > 0; o >>= 1) x += __shfl_xor_sync(0x0000ffffu, x, o);
        if (t == 0) out[0] = x * (1.f / NROWS);
    }
}

// ===========================================================================
extern "C" void kernel_launch(void* const* d_in, const int* in_sizes, int n_in,
                              void* d_out, int out_size) {
    const float* emb = (const float*)d_in[0];
    const float* w   = (const float*)d_in[1];
    const float* b   = (const float*)d_in[2];

    cudaFuncSetAttribute(k_gemm_softmax,
                         cudaFuncAttributeMaxDynamicSharedMemorySize, SMEM2_BYTES);

    k_centroids<<<NS, 128>>>(emb, w, b);
    k_gemm_softmax<<<NROWS / BM, 256, SMEM2_BYTES>>>(w, b);
    k_reduce<<<1, 512>>>((float*)d_out);
}

// round 4
// speedup vs baseline: 5.3715x; 5.3715x over previous
#include <cuda_runtime.h>
#include <cuda_bf16.h>
#include <cstdint>

// ---------------------------------------------------------------------------
// GE2E loss, N_SPK=1024, N_UTT=32, D=128.
// Route: bf16 mma.sync (HMMA) GEMM of ehat[32768x128] x chat^T[128x1024],
// with w*log2e folded into ehat and b*log2e folded into accumulator init, so
// accums are t = log2(exp(logit)). Fused ex2 row-sum; own-column correction
// applied once at the end via precomputed ecorr = exp(ol) - exp(l_full).
// ---------------------------------------------------------------------------

#define NS 1024
#define NU 32
#define DD 128
#define NROWS (NS * NU)          // 32768
#define EPS 1e-8f
#define L2E 1.4426950408889634f

// scratch globals
__device__ __align__(16) __nv_bfloat16 g_ehatb[NROWS * DD];   // 8 MB (pre-scaled by w*log2e)
__device__ __align__(16) __nv_bfloat16 g_chatb[NS * DD];      // 256 KB
__device__ __align__(16) float2 g_own[NROWS];                 // (ol, ecorr)
__device__ __align__(16) float g_partial[NROWS / 128];        // 256

// ---------------- helpers ---------------------------------------------------
__device__ __forceinline__ uint32_t smem_u32(const void* p) {
    uint32_t a;
    asm("{ .reg .u64 t; cvta.to.shared.u64 t, %1; cvt.u32.u64 %0, t; }"
        : "=r"(a) : "l"(p));
    return a;
}
#define CP_ASYNC16(dst_u32, src_ptr) \
    asm volatile("cp.async.ca.shared.global [%0], [%1], 16;" :: "r"(dst_u32), "l"(src_ptr))
#define CP_COMMIT() asm volatile("cp.async.commit_group;")
#define CP_WAIT(n)  asm volatile("cp.async.wait_group %0;" :: "n"(n))

__device__ __forceinline__ void ldsm_x4(uint32_t addr, uint32_t& r0, uint32_t& r1,
                                        uint32_t& r2, uint32_t& r3) {
    asm volatile("ldmatrix.sync.aligned.m8n8.x4.shared.b16 {%0,%1,%2,%3}, [%4];"
                 : "=r"(r0), "=r"(r1), "=r"(r2), "=r"(r3) : "r"(addr));
}
__device__ __forceinline__ void mma16816(float* d, const uint32_t* a,
                                         uint32_t b0, uint32_t b1) {
    asm volatile(
        "mma.sync.aligned.m16n8k16.row.col.f32.bf16.bf16.f32 "
        "{%0,%1,%2,%3}, {%4,%5,%6,%7}, {%8,%9}, {%0,%1,%2,%3};"
        : "+f"(d[0]), "+f"(d[1]), "+f"(d[2]), "+f"(d[3])
        : "r"(a[0]), "r"(a[1]), "r"(a[2]), "r"(a[3]), "r"(b0), "r"(b1));
}

// stage a 128x128 bf16 tile (row-major, 256B rows, contiguous 32KB) into smem
// with XOR-16B swizzle: chunk (r, c) -> r*256 + ((c ^ (r&7)) << 4).
__device__ __forceinline__ void stage_tile(uint32_t sdst, const char* src, int tid) {
#pragma unroll
    for (int i = 0; i < 8; i++) {
        uint32_t q = (uint32_t)tid + i * 256u;       // 0..2047 16B chunks
        uint32_t r = q >> 4, c = q & 15u;
        uint32_t sw = r * 256u + ((c ^ (r & 7u)) << 4);
        CP_ASYNC16(sdst + sw, src + (size_t)q * 16);
    }
}

// ===========================================================================
// Kernel 1: centroids -> ehat (scaled by w*log2e, bf16), chat bf16,
//           per-row (ol, ecorr = exp(ol) - exp(l_full))
// ===========================================================================
__global__ void __launch_bounds__(128) k_prep(const float* __restrict__ emb,
                                              const float* __restrict__ wp,
                                              const float* __restrict__ bp) {
    __shared__ float es[NU][DD];
    __shared__ float S[DD];
    __shared__ float red[4];
    __shared__ float s2_sh;
    __shared__ float en_inv[NU];

    const int n = blockIdx.x, t = threadIdx.x;
    const float* base = emb + (size_t)n * NU * DD;

    float s = 0.f;
#pragma unroll
    for (int m = 0; m < NU; m++) {
        float v = base[m * DD + t];
        es[m][t] = v;
        s += v;
    }
    S[t] = s;
    float v = s * s;
#pragma unroll
    for (int o = 16; o > 0; o >>= 1) v += __shfl_xor_sync(0xffffffffu, v, o);
    if ((t & 31) == 0) red[t >> 5] = v;
    __syncthreads();
    if (t == 0) s2_sh = red[0] + red[1] + red[2] + red[3];
    __syncthreads();
    const float S2 = s2_sh;
    const float w = *wp, b = *bp;
    const float cn = fmaxf(sqrtf(S2) * (1.f / NU), EPS);

    g_chatb[n * DD + t] = __float2bfloat16((S[t] * (1.f / NU)) / cn);

    const int wq = t >> 5, lane = t & 31;
#pragma unroll
    for (int mi = 0; mi < 8; mi++) {
        int m = wq * 8 + mi;
        float dot = 0.f, e2 = 0.f;
#pragma unroll
        for (int c = 0; c < 4; c++) {
            float ev = es[m][lane * 4 + c];
            dot += ev * S[lane * 4 + c];
            e2 += ev * ev;
        }
#pragma unroll
        for (int o = 16; o > 0; o >>= 1) {
            dot += __shfl_xor_sync(0xffffffffu, dot, o);
            e2  += __shfl_xor_sync(0xffffffffu, e2, o);
        }
        if (lane == 0) {
            float en = fmaxf(sqrtf(e2), EPS);
            float d2 = fmaxf(S2 - 2.f * dot + e2, 0.f);
            float cen = fmaxf(sqrtf(d2) * (1.f / (NU - 1)), EPS);
            float sim_ex = ((dot - e2) * (1.f / (NU - 1))) / (en * cen);
            float sim_fl = (dot * (1.f / NU)) / (en * cn);
            float ol = w * sim_ex + b;
            float lf = w * sim_fl + b;
            g_own[n * NU + m] = make_float2(ol, __expf(ol) - __expf(lf));
            en_inv[m] = 1.f / en;
        }
    }
    __syncthreads();
    const float wl2e = w * L2E;
#pragma unroll
    for (int m = 0; m < NU; m++)
        g_ehatb[((size_t)n * NU + m) * DD + t] =
            __float2bfloat16(es[m][t] * en_inv[m] * wl2e);
}

// ===========================================================================
// Kernel 2: HMMA GEMM 128 rows/CTA x 1024 cols, fused ex2 row-sum + loss.
// 256 thr = 8 warps (4 m x 2 n); warp tile 32x64; 8 col-chunks of 128,
// double-buffered cp.async.
// ===========================================================================
#define SMEM_GEMM (1024 + 3 * 32768)

__global__ void __launch_bounds__(256, 2) k_gemm(const float* __restrict__ bp) {
    extern __shared__ char smc[];
    __shared__ float rowsum[128][2];
    __shared__ float redp[8];

    uint32_t sbase = (smem_u32(smc) + 1023u) & ~1023u;
    const uint32_t sA = sbase, sB0 = sbase + 32768u, sB1 = sB0 + 32768u;

    const int tid = threadIdx.x, wq = tid >> 5, lane = tid & 31;
    const int wm = wq >> 1, wn = wq & 1;
    const int rb = blockIdx.x * 128;

    // stage A + B0 (group 0), B1 (group 1)
    stage_tile(sA, (const char*)g_ehatb + (size_t)rb * 256, tid);
    stage_tile(sB0, (const char*)g_chatb, tid);
    CP_COMMIT();
    stage_tile(sB1, (const char*)g_chatb + 32768, tid);
    CP_COMMIT();

    const float bl2e = (*bp) * L2E;

    // ldmatrix address precompute
    const uint32_t hxA = (uint32_t)(lane >> 4);              // 0/1 (k half)
    const uint32_t rA = (uint32_t)(wm * 32 + (lane & 15));
    const uint32_t rxA = rA & 7u;
    const uint32_t baseA0 = sA + rA * 256u;
    const uint32_t baseA1 = baseA0 + 16u * 256u;
    uint32_t offB[4];
#pragma unroll
    for (int p = 0; p < 4; p++) {
        uint32_t nB = (uint32_t)(wn * 64 + p * 16 + (lane & 7) + ((lane >> 4) << 3));
        offB[p] = nB * 256u;
    }
    const uint32_t kxB = (uint32_t)((lane >> 3) & 1);
    const uint32_t rxB = (uint32_t)(lane & 7);

    float racc[4] = {0.f, 0.f, 0.f, 0.f};

    for (int ci = 0; ci < 8; ci++) {
        if (ci < 7) { CP_WAIT(1); } else { CP_WAIT(0); }
        __syncthreads();
        const uint32_t sB = (ci & 1) ? sB1 : sB0;

        float d[2][8][4];
#pragma unroll
        for (int mt = 0; mt < 2; mt++)
#pragma unroll
            for (int nt = 0; nt < 8; nt++)
#pragma unroll
                for (int e = 0; e < 4; e++) d[mt][nt][e] = bl2e;

#pragma unroll
        for (int k = 0; k < 8; k++) {
            uint32_t a0[4], a1[4], bfr[16];
            uint32_t ca = (((uint32_t)(2 * k) + hxA) ^ rxA) << 4;
            ldsm_x4(baseA0 + ca, a0[0], a0[1], a0[2], a0[3]);
            ldsm_x4(baseA1 + ca, a1[0], a1[1], a1[2], a1[3]);
            uint32_t cb = (((uint32_t)(2 * k) + kxB) ^ rxB) << 4;
#pragma unroll
            for (int p = 0; p < 4; p++)
                ldsm_x4(sB + offB[p] + cb,
                        bfr[4 * p], bfr[4 * p + 1], bfr[4 * p + 2], bfr[4 * p + 3]);
#pragma unroll
            for (int nt = 0; nt < 8; nt++) {
                mma16816(d[0][nt], a0, bfr[2 * nt], bfr[2 * nt + 1]);
                mma16816(d[1][nt], a1, bfr[2 * nt], bfr[2 * nt + 1]);
            }
        }

        __syncthreads();               // everyone done reading buf[ci&1]
        if (ci + 2 < 8) {              // refill it with B[ci+2]
            stage_tile((ci & 1) ? sB1 : sB0,
                       (const char*)g_chatb + (size_t)(ci + 2) * 32768, tid);
            CP_COMMIT();
        }

        // epilogue: exp-sum (accum regs are t = log2(exp(logit)))
#pragma unroll
        for (int mt = 0; mt < 2; mt++)
#pragma unroll
            for (int nt = 0; nt < 8; nt++)
#pragma unroll
                for (int e = 0; e < 4; e++) {
                    float ev;
                    asm("ex2.approx.ftz.f32 %0, %1;" : "=f"(ev) : "f"(d[mt][nt][e]));
                    racc[mt * 2 + (e >> 1)] += ev;
                }
    }

    // reduce over the 4 lanes of each row-group (lane bits 0,1)
#pragma unroll
    for (int j = 0; j < 4; j++) {
        racc[j] += __shfl_xor_sync(0xffffffffu, racc[j], 1);
        racc[j] += __shfl_xor_sync(0xffffffffu, racc[j], 2);
    }
    if ((lane & 3) == 0) {
        int g = lane >> 2;
#pragma unroll
        for (int j = 0; j < 4; j++) {
            int row = wm * 32 + (j >> 1) * 16 + (j & 1) * 8 + g;
            rowsum[row][wn] = racc[j];
        }
    }
    __syncthreads();

    // per-row loss + block reduce (deterministic)
    float val = 0.f;
    if (tid < 128) {
        float Ssum = rowsum[tid][0] + rowsum[tid][1];
        float2 oc = g_own[rb + tid];
        val = __logf(Ssum + oc.y) - oc.x;
    }
#pragma unroll
    for (int o = 16; o > 0; o >>= 1) val += __shfl_xor_sync(0xffffffffu, val, o);
    if (lane == 0) redp[wq] = val;
    __syncthreads();
    if (tid == 0) {
        float tsum = 0.f;
#pragma unroll
        for (int i = 0; i < 8; i++) tsum += redp[i];
        g_partial[blockIdx.x] = tsum;
    }
}

// ===========================================================================
// Kernel 3: reduce 256 partials -> mean
// ===========================================================================
__global__ void __launch_bounds__(256) k_reduce(float* __restrict__ out) {
    const int t = threadIdx.x;
    float v = g_partial[t];
#pragma unroll
    for (int o = 16; o > 0; o >>= 1) v += __shfl_xor_sync(0xffffffffu, v, o);
    __shared__ float red[8];
    if ((t & 31) == 0) red[t >> 5] = v;
    __syncthreads();
    if (t == 0) {
        float x = 0.f;
#pragma unroll
        for (int i = 0; i < 8; i++) x += red[i];
        out[0] = x * (1.f / NROWS);
    }
}

// ===========================================================================
extern "C" void kernel_launch(void* const* d_in, const int* in_sizes, int n_in,
                              void* d_out, int out_size) {
    const float* emb = (const float*)d_in[0];
    const float* w   = (const float*)d_in[1];
    const float* b   = (const float*)d_in[2];

    cudaFuncSetAttribute(k_gemm, cudaFuncAttributeMaxDynamicSharedMemorySize,
                         SMEM_GEMM);

    k_prep<<<NS, 128>>>(emb, w, b);
    k_gemm<<<NROWS / 128, 256, SMEM_GEMM>>>(b);
    k_reduce<<<1, 256>>>((float*)d_out);
}